// round 3
// baseline (speedup 1.0000x reference)
#include <cuda_runtime.h>
#include <cuda_bf16.h>
#include <cstdint>

#define T_TOK 8192
#define HID   2048
#define OUTC  3072
#define ACOLS 384
#define NPAD  3456        // OUTC + ACOLS, = 27 * 128
#define BM 128
#define BN 128
#define BK 64

// ---------------- scratch (device globals; no runtime alloc) ----------------
__device__ __align__(128) __nv_bfloat16 g_xh[(size_t)T_TOK*HID];
__device__ __align__(128) __nv_bfloat16 g_xl[(size_t)T_TOK*HID];
__device__ __align__(128) __nv_bfloat16 g_wh[(size_t)NPAD*HID];
__device__ __align__(128) __nv_bfloat16 g_wl[(size_t)NPAD*HID];
__device__ __align__(128) __nv_bfloat16 g_h2h[(size_t)T_TOK*ACOLS];
__device__ __align__(128) __nv_bfloat16 g_h2l[(size_t)T_TOK*ACOLS];
__device__ __align__(128) __nv_bfloat16 g_bh[(size_t)3072*128];
__device__ __align__(128) __nv_bfloat16 g_bl[(size_t)3072*128];
__device__ int g_is64;

#define DINL __device__ __forceinline__

DINL uint32_t smem_u32(const void* p){ uint32_t a;
  asm("{ .reg .u64 t; cvta.to.shared.u64 t, %1; cvt.u32.u64 %0, t; }":"=r"(a):"l"(p)); return a; }

DINL uint32_t swz(uint32_t off){ return off ^ ((off>>3)&0x70); }

DINL void ldmx4(uint32_t* r, uint32_t addr){
  asm volatile("ldmatrix.sync.aligned.m8n8.x4.shared.b16 {%0,%1,%2,%3}, [%4];"
    : "=r"(r[0]),"=r"(r[1]),"=r"(r[2]),"=r"(r[3]) : "r"(addr));
}

DINL void mma16816(float* c, const uint32_t* a, const uint32_t* b){
  asm volatile("mma.sync.aligned.m16n8k16.row.col.f32.bf16.bf16.f32 "
    "{%0,%1,%2,%3},{%4,%5,%6,%7},{%8,%9},{%0,%1,%2,%3};"
    : "+f"(c[0]),"+f"(c[1]),"+f"(c[2]),"+f"(c[3])
    : "r"(a[0]),"r"(a[1]),"r"(a[2]),"r"(a[3]),"r"(b[0]),"r"(b[1]));
}

#define CPA_COMMIT() asm volatile("cp.async.commit_group;\n":::"memory")
#define CPA_WAIT1()  asm volatile("cp.async.wait_group 1;\n":::"memory")

// load 128 x 64 bf16 (128B rows) into SW128-swizzled SMEM via cp.async; 256 threads
DINL void load_tile(uint32_t dst, const __nv_bfloat16* g, long rowBase, int ld, int k0, int tid){
  const char* s0 = (const char*)(g + rowBase*(long)ld + k0);
  const long rb = (long)ld*2;
  #pragma unroll
  for(int c=tid; c<128*8; c+=256){
    int row=c>>3, ck=c&7;
    uint32_t off=(uint32_t)(row*128+ck*16);
    const void* src = s0 + (long)row*rb + ck*16;
    asm volatile("cp.async.cg.shared.global [%0], [%1], 16;\n"::"r"(dst+swz(off)),"l"(src):"memory");
  }
}

static constexpr uint32_t TILE_B = 128*128;       // 16 KB per tile
static constexpr uint32_t STAGE  = 4*TILE_B;      // Ah, Al, Bh, Bl = 64 KB
static constexpr uint32_t SMEM_TOTAL = 3*STAGE;   // 192 KB, 3 stages

// MODE 1: GEMM1 epilogue (y if nB<OUTC else masked/scaled H2 split write)
// MODE 2: out[row, outOff+col] += acc
template<int MODE>
__global__ void __launch_bounds__(256,1)
gemm_k(const __nv_bfloat16* __restrict__ Ah, const __nv_bfloat16* __restrict__ Al, int lda,
       const __nv_bfloat16* __restrict__ Bh, const __nv_bfloat16* __restrict__ Bl, int ldb,
       float* __restrict__ out, int outOff, int NK,
       const unsigned int* __restrict__ tts, const float* __restrict__ scal,
       __nv_bfloat16* __restrict__ h2h, __nv_bfloat16* __restrict__ h2l){
  extern __shared__ __align__(1024) char smem[];
  const uint32_t sb = smem_u32(smem);
  const int tid=threadIdx.x, lane=tid&31, wid=tid>>5;
  const int wm=wid>>2, wn=wid&3;                 // 2 x 4 warp grid -> m64 x n32 warp tile
  const long mB=(long)blockIdx.y*BM, nB=(long)blockIdx.x*BN;

  auto st=[&](int s){ return sb + (uint32_t)s*STAGE; };
  auto load_st=[&](int s,int ki){
    uint32_t a=st(s); int k0=ki*BK;
    load_tile(a,          Ah, mB, lda, k0, tid);
    load_tile(a+TILE_B,   Al, mB, lda, k0, tid);
    load_tile(a+2*TILE_B, Bh, nB, ldb, k0, tid);
    load_tile(a+3*TILE_B, Bl, nB, ldb, k0, tid);
  };

  float c[4][4][4];
  #pragma unroll
  for(int i=0;i<4;i++)
    #pragma unroll
    for(int j=0;j<4;j++)
      #pragma unroll
      for(int e=0;e<4;e++) c[i][j][e]=0.f;

  // per-thread ldmatrix address components
  const int rowA = (lane&15);
  const int cA   = (lane>>4);
  const int rowB = (lane&7) + ((lane>>4)&1)*8;
  const int cB   = (lane>>3)&1;

  load_st(0,0); CPA_COMMIT();
  load_st(1,1); CPA_COMMIT();

  #pragma unroll 1
  for(int ki=0; ki<NK; ki++){
    CPA_WAIT1();
    __syncthreads();
    if(ki+2<NK) load_st((ki+2)%3, ki+2);
    CPA_COMMIT();

    const uint32_t a0 = st(ki%3);
    #pragma unroll 1
    for(int kk=0; kk<4; kk++){
      uint32_t ah[4][4], al[4][4], bh[4][2], bl[4][2];
      #pragma unroll
      for(int mt=0; mt<4; mt++){
        uint32_t off=(uint32_t)((wm*64+mt*16+rowA)*128 + (kk*2+cA)*16);
        ldmx4(ah[mt], a0 + swz(off));
        ldmx4(al[mt], a0 + TILE_B + swz(off));
      }
      #pragma unroll
      for(int p=0; p<2; p++){
        uint32_t off=(uint32_t)((wn*32+p*16+rowB)*128 + (kk*2+cB)*16);
        uint32_t t[4], u[4];
        ldmx4(t, a0 + 2*TILE_B + swz(off));
        ldmx4(u, a0 + 3*TILE_B + swz(off));
        bh[2*p][0]=t[0]; bh[2*p][1]=t[1]; bh[2*p+1][0]=t[2]; bh[2*p+1][1]=t[3];
        bl[2*p][0]=u[0]; bl[2*p][1]=u[1]; bl[2*p+1][0]=u[2]; bl[2*p+1][1]=u[3];
      }
      #pragma unroll
      for(int nt=0; nt<4; nt++)
        #pragma unroll
        for(int mt=0; mt<4; mt++) mma16816(c[mt][nt], ah[mt], bh[nt]);   // hh
      #pragma unroll
      for(int nt=0; nt<4; nt++)
        #pragma unroll
        for(int mt=0; mt<4; mt++) mma16816(c[mt][nt], ah[mt], bl[nt]);   // h*l
      #pragma unroll
      for(int nt=0; nt<4; nt++)
        #pragma unroll
        for(int mt=0; mt<4; mt++) mma16816(c[mt][nt], al[mt], bh[nt]);   // l*h
    }
  }

  // ------------- epilogue -------------
  const int r0 = wm*64 + (lane>>2);
  const int cc0 = wn*32 + (lane&3)*2;
  if(MODE==1 && nB>=OUTC){
    #pragma unroll
    for(int mt=0; mt<4; mt++)
      #pragma unroll
      for(int h=0; h<2; h++){
        long row = mB + r0 + mt*16 + h*8;
        int slot = g_is64 ? (int)tts[2*row] : (int)tts[row];
        float sc = scal[slot];
        #pragma unroll
        for(int nt=0; nt<4; nt++){
          int a = (int)(nB-OUTC) + cc0 + nt*8;
          int l = (a>>4)&7;
          float v0 = (l==slot)? sc*c[mt][nt][h*2]   : 0.f;
          float v1 = (l==slot)? sc*c[mt][nt][h*2+1] : 0.f;
          __nv_bfloat16 h0=__float2bfloat16_rn(v0), h1=__float2bfloat16_rn(v1);
          __nv_bfloat16 e0=__float2bfloat16_rn(v0-__bfloat162float(h0));
          __nv_bfloat16 e1=__float2bfloat16_rn(v1-__bfloat162float(h1));
          uint32_t ph=(uint32_t)__bfloat16_as_ushort(h0) | ((uint32_t)__bfloat16_as_ushort(h1)<<16);
          uint32_t pl=(uint32_t)__bfloat16_as_ushort(e0) | ((uint32_t)__bfloat16_as_ushort(e1)<<16);
          *(uint32_t*)(h2h + row*ACOLS + a) = ph;
          *(uint32_t*)(h2l + row*ACOLS + a) = pl;
        }
      }
  } else if(MODE==1){
    #pragma unroll
    for(int mt=0; mt<4; mt++)
      #pragma unroll
      for(int h=0; h<2; h++){
        long row = mB + r0 + mt*16 + h*8;
        float2* base=(float2*)(out + row*OUTC + nB + cc0);
        #pragma unroll
        for(int nt=0; nt<4; nt++)
          base[nt*4] = make_float2(c[mt][nt][h*2], c[mt][nt][h*2+1]);
      }
  } else {
    #pragma unroll
    for(int mt=0; mt<4; mt++)
      #pragma unroll
      for(int h=0; h<2; h++){
        long row = mB + r0 + mt*16 + h*8;
        float2* base=(float2*)(out + row*OUTC + outOff + nB + cc0);
        #pragma unroll
        for(int nt=0; nt<4; nt++){
          float2 o=base[nt*4];
          o.x+=c[mt][nt][h*2]; o.y+=c[mt][nt][h*2+1];
          base[nt*4]=o;
        }
      }
  }
}

// ---------------- prep kernels ----------------
__global__ void k_split_x(const float* __restrict__ x, __nv_bfloat16* __restrict__ xh,
                          __nv_bfloat16* __restrict__ xl, int n4){
  int i=blockIdx.x*blockDim.x+threadIdx.x; if(i>=n4) return;
  float4 v=((const float4*)x)[i]; float vv[4]={v.x,v.y,v.z,v.w};
  ushort4 hv,lv; unsigned short* hp=&hv.x; unsigned short* lp=&lv.x;
  #pragma unroll
  for(int j=0;j<4;j++){
    __nv_bfloat16 h=__float2bfloat16_rn(vv[j]);
    __nv_bfloat16 l=__float2bfloat16_rn(vv[j]-__bfloat162float(h));
    hp[j]=__bfloat16_as_ushort(h); lp[j]=__bfloat16_as_ushort(l);
  }
  ((ushort4*)xh)[i]=hv; ((ushort4*)xl)[i]=lv;
}

// W_cat rows: [0,OUTC)=weight; [OUTC,3456)=lora_A with a = g*128 + l*16 + r
__global__ void k_build_w(const float* __restrict__ w, const float* __restrict__ la,
                          __nv_bfloat16* __restrict__ wh, __nv_bfloat16* __restrict__ wl){
  long i=(long)blockIdx.x*blockDim.x+threadIdx.x; if(i>=(long)NPAD*HID) return;
  int row=(int)(i>>11), k=(int)(i&2047);
  float v;
  if(row<OUTC) v=w[i];
  else{
    int a=row-OUTC, g=a>>7, l=(a>>4)&7, r=a&15;
    v=la[(((long)l*3+g)*16+r)*HID+k];
  }
  __nv_bfloat16 h=__float2bfloat16_rn(v);
  wh[i]=h; wl[i]=__float2bfloat16_rn(v-__bfloat162float(h));
}

// Ball rows: o<2048: Bq; o<2560: Bk; else Bv. cols: l*16+r (128 wide)
__global__ void k_build_ball(const float* __restrict__ bq, const float* __restrict__ bk,
                             const float* __restrict__ bv, __nv_bfloat16* __restrict__ bh,
                             __nv_bfloat16* __restrict__ bl){
  int i=blockIdx.x*blockDim.x+threadIdx.x; if(i>=3072*128) return;
  int o=i>>7, a=i&127, l=a>>4, r=a&15;
  float v;
  if(o<2048)      v=bq[((long)l*2048+o)*16+r];
  else if(o<2560) v=bk[((long)l*512+(o-2048))*16+r];
  else            v=bv[((long)l*512+(o-2560))*16+r];
  __nv_bfloat16 h=__float2bfloat16_rn(v);
  bh[i]=h; bl[i]=__float2bfloat16_rn(v-__bfloat162float(h));
}

// token_to_slot dtype sniff: slots<8, so int64 => all odd 32-bit words in [0, 2*T) are 0
__global__ void k_detect(const unsigned int* __restrict__ w){
  __shared__ int found;
  if(threadIdx.x==0) found=0;
  __syncthreads();
  int loc=0;
  for(int i=1+2*(int)threadIdx.x; i<T_TOK; i+=1024) loc|=(w[i]!=0u);
  if(loc) atomicOr(&found,1);
  __syncthreads();
  if(threadIdx.x==0) g_is64 = found?0:1;
}

extern "C" void kernel_launch(void* const* d_in, const int* in_sizes, int n_in,
                              void* d_out, int out_size){
  (void)in_sizes; (void)n_in; (void)out_size;
  const float* x =(const float*)d_in[0];
  const float* w =(const float*)d_in[1];
  const float* la=(const float*)d_in[2];
  const float* bq=(const float*)d_in[3];
  const float* bk=(const float*)d_in[4];
  const float* bv=(const float*)d_in[5];
  const float* sc=(const float*)d_in[6];
  const unsigned int* tt=(const unsigned int*)d_in[7];
  float* out=(float*)d_out;

  void *xh,*xl,*wh,*wl,*h2h,*h2l,*bh,*bl;
  cudaGetSymbolAddress(&xh,g_xh);   cudaGetSymbolAddress(&xl,g_xl);
  cudaGetSymbolAddress(&wh,g_wh);   cudaGetSymbolAddress(&wl,g_wl);
  cudaGetSymbolAddress(&h2h,g_h2h); cudaGetSymbolAddress(&h2l,g_h2l);
  cudaGetSymbolAddress(&bh,g_bh);   cudaGetSymbolAddress(&bl,g_bl);

  cudaFuncSetAttribute(gemm_k<1>, cudaFuncAttributeMaxDynamicSharedMemorySize, SMEM_TOTAL);
  cudaFuncSetAttribute(gemm_k<2>, cudaFuncAttributeMaxDynamicSharedMemorySize, SMEM_TOTAL);

  k_detect<<<1,512>>>(tt);
  k_split_x<<<(T_TOK*HID/4+255)/256,256>>>(x,(__nv_bfloat16*)xh,(__nv_bfloat16*)xl,T_TOK*HID/4);
  k_build_w<<<((long)NPAD*HID+255)/256,256>>>(w,la,(__nv_bfloat16*)wh,(__nv_bfloat16*)wl);
  k_build_ball<<<(3072*128+255)/256,256>>>(bq,bk,bv,(__nv_bfloat16*)bh,(__nv_bfloat16*)bl);

  // GEMM1: [8192 x 3456] = Xsplit @ Wcat^T ; epilogue -> y (cols<3072) + H2 (cols>=3072)
  gemm_k<1><<<dim3(NPAD/BN, T_TOK/BM), 256, SMEM_TOTAL>>>(
      (const __nv_bfloat16*)xh,(const __nv_bfloat16*)xl, HID,
      (const __nv_bfloat16*)wh,(const __nv_bfloat16*)wl, HID,
      out, 0, HID/BK, tt, sc, (__nv_bfloat16*)h2h,(__nv_bfloat16*)h2l);

  // GEMM2 (delta accumulate): dq, dk, dv — K=128 each (NK=2)
  const __nv_bfloat16* H2h=(const __nv_bfloat16*)h2h;
  const __nv_bfloat16* H2l=(const __nv_bfloat16*)h2l;
  const __nv_bfloat16* Bq2=(const __nv_bfloat16*)bh;
  const __nv_bfloat16* Bq2l=(const __nv_bfloat16*)bl;
  gemm_k<2><<<dim3(2048/BN, T_TOK/BM), 256, SMEM_TOTAL>>>(
      H2h, H2l, ACOLS, Bq2, Bq2l, 128, out, 0, 2, tt, sc, nullptr, nullptr);
  gemm_k<2><<<dim3(512/BN, T_TOK/BM), 256, SMEM_TOTAL>>>(
      H2h+128, H2l+128, ACOLS, Bq2+(long)2048*128, Bq2l+(long)2048*128, 128,
      out, 2048, 2, tt, sc, nullptr, nullptr);
  gemm_k<2><<<dim3(512/BN, T_TOK/BM), 256, SMEM_TOTAL>>>(
      H2h+256, H2l+256, ACOLS, Bq2+(long)2560*128, Bq2l+(long)2560*128, 128,
      out, 2560, 2, tt, sc, nullptr, nullptr);
}

// round 4
// speedup vs baseline: 2.0028x; 2.0028x over previous
#include <cuda_runtime.h>
#include <cuda_fp16.h>
#include <cstdint>

#define T_TOK 8192
#define HID   2048
#define OUTC  3072
#define ACOLS 384
#define NPAD  3456        // OUTC + ACOLS = 27 * 128
#define BM 128
#define BN 128
#define BK 64

// ---------------- scratch (device globals; no runtime alloc) ----------------
__device__ __align__(128) __half g_xf[(size_t)T_TOK*HID];
__device__ __align__(128) __half g_wf[(size_t)NPAD*HID];
__device__ __align__(128) __half g_h2[(size_t)T_TOK*ACOLS];
__device__ __align__(128) __half g_bf[(size_t)3072*128];
__device__ int g_is64;

#define DINL __device__ __forceinline__

DINL uint32_t smem_u32(const void* p){ uint32_t a;
  asm("{ .reg .u64 t; cvta.to.shared.u64 t, %1; cvt.u32.u64 %0, t; }":"=r"(a):"l"(p)); return a; }

DINL uint32_t swz(uint32_t off){ return off ^ ((off>>3)&0x70); }

DINL void ldmx4(uint32_t* r, uint32_t addr){
  asm volatile("ldmatrix.sync.aligned.m8n8.x4.shared.b16 {%0,%1,%2,%3}, [%4];"
    : "=r"(r[0]),"=r"(r[1]),"=r"(r[2]),"=r"(r[3]) : "r"(addr));
}

DINL void mma16816(float* c, const uint32_t* a, const uint32_t* b){
  asm volatile("mma.sync.aligned.m16n8k16.row.col.f32.f16.f16.f32 "
    "{%0,%1,%2,%3},{%4,%5,%6,%7},{%8,%9},{%0,%1,%2,%3};"
    : "+f"(c[0]),"+f"(c[1]),"+f"(c[2]),"+f"(c[3])
    : "r"(a[0]),"r"(a[1]),"r"(a[2]),"r"(a[3]),"r"(b[0]),"r"(b[1]));
}

#define CPA_COMMIT() asm volatile("cp.async.commit_group;\n":::"memory")
#define CPA_WAIT2()  asm volatile("cp.async.wait_group 2;\n":::"memory")

// load 128 x 64 fp16 (128B rows) into SW128-swizzled SMEM via cp.async; 256 threads
DINL void load_tile(uint32_t dst, const __half* g, long rowBase, int ld, int k0, int tid){
  const char* s0 = (const char*)(g + rowBase*(long)ld + k0);
  const long rb = (long)ld*2;
  #pragma unroll
  for(int c=tid; c<128*8; c+=256){
    int row=c>>3, ck=c&7;
    uint32_t off=(uint32_t)(row*128+ck*16);
    const void* src = s0 + (long)row*rb + ck*16;
    asm volatile("cp.async.cg.shared.global [%0], [%1], 16;\n"::"r"(dst+swz(off)),"l"(src):"memory");
  }
}

static constexpr uint32_t TILE_B = 128*128;        // 16 KB per tile
static constexpr uint32_t STAGE  = 2*TILE_B;       // A + B = 32 KB
static constexpr int      NSTG   = 4;
static constexpr uint32_t SMEM_TOTAL = NSTG*STAGE; // 128 KB

// MODE 1: GEMM1 epilogue (y if nB<OUTC else masked/scaled H2 fp16 write)
// MODE 2: out[row, outOff+col] += acc
template<int MODE>
__global__ void __launch_bounds__(256,1)
gemm_k(const __half* __restrict__ A, int lda,
       const __half* __restrict__ B, int ldb,
       float* __restrict__ out, int outOff, int NK,
       const unsigned int* __restrict__ tts, const float* __restrict__ scal,
       __half* __restrict__ h2){
  extern __shared__ __align__(1024) char smem[];
  const uint32_t sb = smem_u32(smem);
  const int tid=threadIdx.x, lane=tid&31, wid=tid>>5;
  const int wm=wid>>2, wn=wid&3;                 // 2 x 4 warp grid -> m64 x n32 warp tile
  const long mB=(long)blockIdx.y*BM, nB=(long)blockIdx.x*BN;

  auto st=[&](int s){ return sb + (uint32_t)s*STAGE; };
  auto load_st=[&](int s,int ki){
    uint32_t a=st(s); int k0=ki*BK;
    load_tile(a,        A, mB, lda, k0, tid);
    load_tile(a+TILE_B, B, nB, ldb, k0, tid);
  };

  float c[4][4][4];
  #pragma unroll
  for(int i=0;i<4;i++)
    #pragma unroll
    for(int j=0;j<4;j++)
      #pragma unroll
      for(int e=0;e<4;e++) c[i][j][e]=0.f;

  const int rowA = (lane&15);
  const int cA   = (lane>>4);
  const int rowB = (lane&7) + ((lane>>4)&1)*8;
  const int cB   = (lane>>3)&1;

  // prologue: up to 3 stages in flight (always 3 commits for group accounting)
  #pragma unroll
  for(int s=0;s<3;s++){ if(s<NK) load_st(s,s); CPA_COMMIT(); }

  #pragma unroll 1
  for(int ki=0; ki<NK; ki++){
    CPA_WAIT2();
    __syncthreads();
    if(ki+3<NK) load_st((ki+3)%NSTG, ki+3);
    CPA_COMMIT();

    const uint32_t a0 = st(ki%NSTG);
    #pragma unroll 1
    for(int kk=0; kk<4; kk++){
      uint32_t af[4][4], bf[4][2];
      #pragma unroll
      for(int mt=0; mt<4; mt++){
        uint32_t off=(uint32_t)((wm*64+mt*16+rowA)*128 + (kk*2+cA)*16);
        ldmx4(af[mt], a0 + swz(off));
      }
      #pragma unroll
      for(int p=0; p<2; p++){
        uint32_t off=(uint32_t)((wn*32+p*16+rowB)*128 + (kk*2+cB)*16);
        uint32_t t[4];
        ldmx4(t, a0 + TILE_B + swz(off));
        bf[2*p][0]=t[0]; bf[2*p][1]=t[1]; bf[2*p+1][0]=t[2]; bf[2*p+1][1]=t[3];
      }
      #pragma unroll
      for(int nt=0; nt<4; nt++)
        #pragma unroll
        for(int mt=0; mt<4; mt++) mma16816(c[mt][nt], af[mt], bf[nt]);
    }
  }

  // ------------- epilogue -------------
  const int r0 = wm*64 + (lane>>2);
  const int cc0 = wn*32 + (lane&3)*2;
  if(MODE==1 && nB>=OUTC){
    #pragma unroll
    for(int mt=0; mt<4; mt++)
      #pragma unroll
      for(int h=0; h<2; h++){
        long row = mB + r0 + mt*16 + h*8;
        int slot = g_is64 ? (int)tts[2*row] : (int)tts[row];
        float sc = scal[slot];
        #pragma unroll
        for(int nt=0; nt<4; nt++){
          int a = (int)(nB-OUTC) + cc0 + nt*8;
          int l = (a>>4)&7;
          float v0 = (l==slot)? sc*c[mt][nt][h*2]   : 0.f;
          float v1 = (l==slot)? sc*c[mt][nt][h*2+1] : 0.f;
          __half2 pk = __floats2half2_rn(v0, v1);
          *(__half2*)(h2 + row*ACOLS + a) = pk;
        }
      }
  } else if(MODE==1){
    #pragma unroll
    for(int mt=0; mt<4; mt++)
      #pragma unroll
      for(int h=0; h<2; h++){
        long row = mB + r0 + mt*16 + h*8;
        float2* base=(float2*)(out + row*OUTC + nB + cc0);
        #pragma unroll
        for(int nt=0; nt<4; nt++)
          base[nt*4] = make_float2(c[mt][nt][h*2], c[mt][nt][h*2+1]);
      }
  } else {
    #pragma unroll
    for(int mt=0; mt<4; mt++)
      #pragma unroll
      for(int h=0; h<2; h++){
        long row = mB + r0 + mt*16 + h*8;
        float2* base=(float2*)(out + row*OUTC + outOff + nB + cc0);
        #pragma unroll
        for(int nt=0; nt<4; nt++){
          float2 o=base[nt*4];
          o.x+=c[mt][nt][h*2]; o.y+=c[mt][nt][h*2+1];
          base[nt*4]=o;
        }
      }
  }
}

// ---------------- prep kernels ----------------
__global__ void k_cvt_x(const float* __restrict__ x, __half* __restrict__ xf, int n4){
  int i=blockIdx.x*blockDim.x+threadIdx.x; if(i>=n4) return;
  float4 v=((const float4*)x)[i];
  __half2 a=__floats2half2_rn(v.x,v.y), b=__floats2half2_rn(v.z,v.w);
  ((__half2*)xf)[2*i]=a; ((__half2*)xf)[2*i+1]=b;
}

// W_cat rows: [0,OUTC)=weight; [OUTC,3456)=lora_A with a = g*128 + l*16 + r
__global__ void k_build_w(const float* __restrict__ w, const float* __restrict__ la,
                          __half* __restrict__ wf){
  long i=(long)blockIdx.x*blockDim.x+threadIdx.x; if(i>=(long)NPAD*HID) return;
  int row=(int)(i>>11), k=(int)(i&2047);
  float v;
  if(row<OUTC) v=w[i];
  else{
    int a=row-OUTC, g=a>>7, l=(a>>4)&7, r=a&15;
    v=la[(((long)l*3+g)*16+r)*HID+k];
  }
  wf[i]=__float2half_rn(v);
}

// Ball rows: o<2048: Bq; o<2560: Bk; else Bv. cols: l*16+r (128 wide)
__global__ void k_build_ball(const float* __restrict__ bq, const float* __restrict__ bk,
                             const float* __restrict__ bv, __half* __restrict__ bf){
  int i=blockIdx.x*blockDim.x+threadIdx.x; if(i>=3072*128) return;
  int o=i>>7, a=i&127, l=a>>4, r=a&15;
  float v;
  if(o<2048)      v=bq[((long)l*2048+o)*16+r];
  else if(o<2560) v=bk[((long)l*512+(o-2048))*16+r];
  else            v=bv[((long)l*512+(o-2560))*16+r];
  bf[i]=__float2half_rn(v);
}

// token_to_slot dtype sniff: slots<8, so int64 => all odd 32-bit words in [0, 2*T) are 0
__global__ void k_detect(const unsigned int* __restrict__ w){
  __shared__ int found;
  if(threadIdx.x==0) found=0;
  __syncthreads();
  int loc=0;
  for(int i=1+2*(int)threadIdx.x; i<T_TOK; i+=1024) loc|=(w[i]!=0u);
  if(loc) atomicOr(&found,1);
  __syncthreads();
  if(threadIdx.x==0) g_is64 = found?0:1;
}

extern "C" void kernel_launch(void* const* d_in, const int* in_sizes, int n_in,
                              void* d_out, int out_size){
  (void)in_sizes; (void)n_in; (void)out_size;
  const float* x =(const float*)d_in[0];
  const float* w =(const float*)d_in[1];
  const float* la=(const float*)d_in[2];
  const float* bq=(const float*)d_in[3];
  const float* bk=(const float*)d_in[4];
  const float* bv=(const float*)d_in[5];
  const float* sc=(const float*)d_in[6];
  const unsigned int* tt=(const unsigned int*)d_in[7];
  float* out=(float*)d_out;

  void *xf,*wf,*h2,*bf;
  cudaGetSymbolAddress(&xf,g_xf); cudaGetSymbolAddress(&wf,g_wf);
  cudaGetSymbolAddress(&h2,g_h2); cudaGetSymbolAddress(&bf,g_bf);

  cudaFuncSetAttribute(gemm_k<1>, cudaFuncAttributeMaxDynamicSharedMemorySize, SMEM_TOTAL);
  cudaFuncSetAttribute(gemm_k<2>, cudaFuncAttributeMaxDynamicSharedMemorySize, SMEM_TOTAL);

  k_detect<<<1,512>>>(tt);
  k_cvt_x<<<(T_TOK*HID/4+255)/256,256>>>(x,(__half*)xf,T_TOK*HID/4);
  k_build_w<<<((long)NPAD*HID+255)/256,256>>>(w,la,(__half*)wf);
  k_build_ball<<<(3072*128+255)/256,256>>>(bq,bk,bv,(__half*)bf);

  // GEMM1: [8192 x 3456] = X @ Wcat^T ; epilogue -> y (cols<3072) + H2 (cols>=3072)
  gemm_k<1><<<dim3(NPAD/BN, T_TOK/BM), 256, SMEM_TOTAL>>>(
      (const __half*)xf, HID, (const __half*)wf, HID,
      out, 0, HID/BK, tt, sc, (__half*)h2);

  // GEMM2 (delta accumulate): dq, dk, dv — K=128 each (NK=2)
  const __half* H2=(const __half*)h2;
  const __half* Bf=(const __half*)bf;
  gemm_k<2><<<dim3(2048/BN, T_TOK/BM), 256, SMEM_TOTAL>>>(
      H2, ACOLS, Bf, 128, out, 0, 2, tt, sc, nullptr);
  gemm_k<2><<<dim3(512/BN, T_TOK/BM), 256, SMEM_TOTAL>>>(
      H2+128, ACOLS, Bf+(long)2048*128, 128, out, 2048, 2, tt, sc, nullptr);
  gemm_k<2><<<dim3(512/BN, T_TOK/BM), 256, SMEM_TOTAL>>>(
      H2+256, ACOLS, Bf+(long)2560*128, 128, out, 2560, 2, tt, sc, nullptr);
}

// round 5
// speedup vs baseline: 2.2281x; 1.1125x over previous
#include <cuda_runtime.h>
#include <cuda_fp16.h>
#include <cstdint>

#define T_TOK 8192
#define HID   2048
#define OUTC  3072
#define ACOLS 384
#define KEXT  2176        // HID + 128 appended rank-block
#define BM 128
#define BN 128
#define BK 64

// ---------------- scratch (device globals; no runtime alloc) ----------------
__device__ __align__(128) __half g_xf[(size_t)T_TOK*HID];
__device__ __align__(128) __half g_w2[(size_t)OUTC*KEXT];      // [W | Ball_g] 13.4MB
__device__ __align__(128) __half g_ac[(size_t)ACOLS*HID];      // A_cat 384x2048
__device__ __align__(128) __half g_h2[(size_t)T_TOK*ACOLS];
__device__ int g_is64;

#define DINL __device__ __forceinline__

DINL uint32_t smem_u32(const void* p){ uint32_t a;
  asm("{ .reg .u64 t; cvta.to.shared.u64 t, %1; cvt.u32.u64 %0, t; }":"=r"(a):"l"(p)); return a; }

DINL uint32_t swz(uint32_t off){ return off ^ ((off>>3)&0x70); }

DINL void ldmx4(uint32_t* r, uint32_t addr){
  asm volatile("ldmatrix.sync.aligned.m8n8.x4.shared.b16 {%0,%1,%2,%3}, [%4];"
    : "=r"(r[0]),"=r"(r[1]),"=r"(r[2]),"=r"(r[3]) : "r"(addr));
}

DINL void mma16816(float* c, const uint32_t* a, const uint32_t* b){
  asm volatile("mma.sync.aligned.m16n8k16.row.col.f32.f16.f16.f32 "
    "{%0,%1,%2,%3},{%4,%5,%6,%7},{%8,%9},{%0,%1,%2,%3};"
    : "+f"(c[0]),"+f"(c[1]),"+f"(c[2]),"+f"(c[3])
    : "r"(a[0]),"r"(a[1]),"r"(a[2]),"r"(a[3]),"r"(b[0]),"r"(b[1]));
}

#define CPA_COMMIT() asm volatile("cp.async.commit_group;\n":::"memory")
#define CPA_WAIT2()  asm volatile("cp.async.wait_group 2;\n":::"memory")

// load 128 x 64 fp16 (128B rows) into SW128-swizzled SMEM via cp.async; 256 threads
DINL void load_tile(uint32_t dst, const __half* g, long rowBase, int ld, int k0, int tid){
  const char* s0 = (const char*)(g + rowBase*(long)ld + k0);
  const long rb = (long)ld*2;
  #pragma unroll
  for(int c=tid; c<128*8; c+=256){
    int row=c>>3, ck=c&7;
    uint32_t off=(uint32_t)(row*128+ck*16);
    const void* src = s0 + (long)row*rb + ck*16;
    asm volatile("cp.async.cg.shared.global [%0], [%1], 16;\n"::"r"(dst+swz(off)),"l"(src):"memory");
  }
}

static constexpr uint32_t TILE_B = 128*128;        // 16 KB per tile
static constexpr uint32_t STAGE  = 2*TILE_B;       // A + B = 32 KB
static constexpr int      NSTG   = 4;
static constexpr uint32_t SMEM_TOTAL = NSTG*STAGE; // 128 KB

// MODE 1: fused GEMM1 — K = nkx*BK from A, then (NK-nkx)*BK from A2 (H2 slice).
//         Epilogue: plain y store to out (full 3072 cols).
// MODE 3: GEMM0 — epilogue: slot-mask + scale -> H2 fp16 write.
template<int MODE>
__global__ void __launch_bounds__(256,1)
gemm_k(const __half* __restrict__ A, int lda,
       const __half* __restrict__ A2, int lda2,
       const __half* __restrict__ B, int ldb,
       float* __restrict__ out, int NK, int nkx,
       const unsigned int* __restrict__ tts, const float* __restrict__ scal,
       __half* __restrict__ h2){
  extern __shared__ __align__(1024) char smem[];
  const uint32_t sb = smem_u32(smem);
  const int tid=threadIdx.x, lane=tid&31, wid=tid>>5;
  const int wm=wid>>2, wn=wid&3;                 // 2 x 4 warp grid -> m64 x n32 warp tile
  const long mB=(long)blockIdx.y*BM, nB=(long)blockIdx.x*BN;
  // group of this CTA's output-column range (for H2 slice offset)
  const int gofs = (MODE==1) ? ((nB>=2560)?256:((nB>=2048)?128:0)) : 0;

  auto st=[&](int s){ return sb + (uint32_t)s*STAGE; };
  auto load_st=[&](int s,int ki){
    uint32_t a=st(s);
    if(MODE==1 && ki>=nkx) load_tile(a, A2, mB, lda2, gofs + (ki-nkx)*BK, tid);
    else                   load_tile(a, A,  mB, lda,  ki*BK, tid);
    load_tile(a+TILE_B, B, nB, ldb, ki*BK, tid);
  };

  float c[4][4][4];
  #pragma unroll
  for(int i=0;i<4;i++)
    #pragma unroll
    for(int j=0;j<4;j++)
      #pragma unroll
      for(int e=0;e<4;e++) c[i][j][e]=0.f;

  const int rowA = (lane&15);
  const int cA   = (lane>>4);
  const int rowB = (lane&7) + ((lane>>4)&1)*8;
  const int cB   = (lane>>3)&1;

  #pragma unroll
  for(int s=0;s<3;s++){ if(s<NK) load_st(s,s); CPA_COMMIT(); }

  #pragma unroll 1
  for(int ki=0; ki<NK; ki++){
    CPA_WAIT2();
    __syncthreads();
    if(ki+3<NK) load_st((ki+3)%NSTG, ki+3);
    CPA_COMMIT();

    const uint32_t a0 = st(ki%NSTG);
    #pragma unroll 1
    for(int kk=0; kk<4; kk++){
      uint32_t af[4][4], bf[4][2];
      #pragma unroll
      for(int mt=0; mt<4; mt++){
        uint32_t off=(uint32_t)((wm*64+mt*16+rowA)*128 + (kk*2+cA)*16);
        ldmx4(af[mt], a0 + swz(off));
      }
      #pragma unroll
      for(int p=0; p<2; p++){
        uint32_t off=(uint32_t)((wn*32+p*16+rowB)*128 + (kk*2+cB)*16);
        uint32_t t[4];
        ldmx4(t, a0 + TILE_B + swz(off));
        bf[2*p][0]=t[0]; bf[2*p][1]=t[1]; bf[2*p+1][0]=t[2]; bf[2*p+1][1]=t[3];
      }
      #pragma unroll
      for(int nt=0; nt<4; nt++)
        #pragma unroll
        for(int mt=0; mt<4; mt++) mma16816(c[mt][nt], af[mt], bf[nt]);
    }
  }

  // ------------- epilogue -------------
  const int r0 = wm*64 + (lane>>2);
  const int cc0 = wn*32 + (lane&3)*2;
  if(MODE==3){
    #pragma unroll
    for(int mt=0; mt<4; mt++)
      #pragma unroll
      for(int h=0; h<2; h++){
        long row = mB + r0 + mt*16 + h*8;
        int slot = g_is64 ? (int)tts[2*row] : (int)tts[row];
        float sc = scal[slot];
        #pragma unroll
        for(int nt=0; nt<4; nt++){
          int a = (int)nB + cc0 + nt*8;
          int l = (a>>4)&7;
          float v0 = (l==slot)? sc*c[mt][nt][h*2]   : 0.f;
          float v1 = (l==slot)? sc*c[mt][nt][h*2+1] : 0.f;
          *(__half2*)(h2 + row*ACOLS + a) = __floats2half2_rn(v0, v1);
        }
      }
  } else {
    #pragma unroll
    for(int mt=0; mt<4; mt++)
      #pragma unroll
      for(int h=0; h<2; h++){
        long row = mB + r0 + mt*16 + h*8;
        float2* base=(float2*)(out + row*OUTC + nB + cc0);
        #pragma unroll
        for(int nt=0; nt<4; nt++)
          base[nt*4] = make_float2(c[mt][nt][h*2], c[mt][nt][h*2+1]);
      }
  }
}

// ---------------- prep kernels ----------------
__global__ void k_cvt_x(const float* __restrict__ x, __half* __restrict__ xf, int n4){
  int i=blockIdx.x*blockDim.x+threadIdx.x; if(i>=n4) return;
  float4 v=((const float4*)x)[i];
  ((__half2*)xf)[2*i]  =__floats2half2_rn(v.x,v.y);
  ((__half2*)xf)[2*i+1]=__floats2half2_rn(v.z,v.w);
}

// W2[o, 0..2047] = weight[o]; W2[o, 2048+j] = Ball_g(o)[o, j], j = l*16+r
__global__ void k_build_w2(const float* __restrict__ w, const float* __restrict__ bq,
                           const float* __restrict__ bk, const float* __restrict__ bv,
                           __half* __restrict__ w2){
  long i=(long)blockIdx.x*blockDim.x+threadIdx.x; if(i>=(long)OUTC*KEXT) return;
  int row=(int)(i/KEXT), k=(int)(i-(long)row*KEXT);
  float v;
  if(k<HID) v=w[(long)row*HID+k];
  else{
    int j=k-HID, l=j>>4, r=j&15;
    if(row<2048)      v=bq[((long)l*2048+row)*16+r];
    else if(row<2560) v=bk[((long)l*512+(row-2048))*16+r];
    else              v=bv[((long)l*512+(row-2560))*16+r];
  }
  w2[i]=__float2half_rn(v);
}

// A_cat rows: a = g*128 + l*16 + r -> lora_A[l, g, r, :]
__global__ void k_build_acat(const float* __restrict__ la, __half* __restrict__ ac){
  int i=blockIdx.x*blockDim.x+threadIdx.x; if(i>=ACOLS*HID) return;
  int row=i>>11, k=i&2047;
  int g=row>>7, l=(row>>4)&7, r=row&15;
  ac[i]=__float2half_rn(la[(((long)l*3+g)*16+r)*HID+k]);
}

// token_to_slot dtype sniff: slots<8, so int64 => all odd 32-bit words in [0, 2*T) are 0
__global__ void k_detect(const unsigned int* __restrict__ w){
  __shared__ int found;
  if(threadIdx.x==0) found=0;
  __syncthreads();
  int loc=0;
  for(int i=1+2*(int)threadIdx.x; i<T_TOK; i+=1024) loc|=(w[i]!=0u);
  if(loc) atomicOr(&found,1);
  __syncthreads();
  if(threadIdx.x==0) g_is64 = found?0:1;
}

extern "C" void kernel_launch(void* const* d_in, const int* in_sizes, int n_in,
                              void* d_out, int out_size){
  (void)in_sizes; (void)n_in; (void)out_size;
  const float* x =(const float*)d_in[0];
  const float* w =(const float*)d_in[1];
  const float* la=(const float*)d_in[2];
  const float* bq=(const float*)d_in[3];
  const float* bk=(const float*)d_in[4];
  const float* bv=(const float*)d_in[5];
  const float* sc=(const float*)d_in[6];
  const unsigned int* tt=(const unsigned int*)d_in[7];
  float* out=(float*)d_out;

  void *xf,*w2,*ac,*h2;
  cudaGetSymbolAddress(&xf,g_xf); cudaGetSymbolAddress(&w2,g_w2);
  cudaGetSymbolAddress(&ac,g_ac); cudaGetSymbolAddress(&h2,g_h2);

  cudaFuncSetAttribute(gemm_k<1>, cudaFuncAttributeMaxDynamicSharedMemorySize, SMEM_TOTAL);
  cudaFuncSetAttribute(gemm_k<3>, cudaFuncAttributeMaxDynamicSharedMemorySize, SMEM_TOTAL);

  k_detect<<<1,512>>>(tt);
  k_cvt_x<<<(T_TOK*HID/4+255)/256,256>>>(x,(__half*)xf,T_TOK*HID/4);
  k_build_acat<<<(ACOLS*HID+255)/256,256>>>(la,(__half*)ac);
  k_build_w2<<<((long)OUTC*KEXT+255)/256,256>>>(w,bq,bk,bv,(__half*)w2);

  // GEMM0: H2[8192 x 384] = mask/scale( X @ A_cat^T )
  gemm_k<3><<<dim3(ACOLS/BN, T_TOK/BM), 256, SMEM_TOTAL>>>(
      (const __half*)xf, HID, nullptr, 0, (const __half*)ac, HID,
      nullptr, HID/BK, HID/BK, tt, sc, (__half*)h2);

  // GEMM1 fused: out[8192 x 3072] = [X | H2_g] @ [W | Ball_g]^T  (K = 2176)
  gemm_k<1><<<dim3(OUTC/BN, T_TOK/BM), 256, SMEM_TOTAL>>>(
      (const __half*)xf, HID, (const __half*)h2, ACOLS, (const __half*)w2, KEXT,
      out, KEXT/BK, HID/BK, tt, sc, nullptr);
}

// round 6
// speedup vs baseline: 2.5936x; 1.1640x over previous
#include <cuda_runtime.h>
#include <cuda_fp16.h>
#include <cstdint>

#define T_TOK 8192
#define HID   2048
#define OUTC  3072
#define ACOLS 384
#define KEXT  2176        // HID + 128 appended rank-block
#define BM 128
#define BN 128
#define BK 64

// ---------------- scratch (device globals; no runtime alloc) ----------------
__device__ __align__(128) __half g_xf[(size_t)T_TOK*HID];
__device__ __align__(128) __half g_w2[(size_t)OUTC*KEXT];      // [W | Ball_g]
__device__ __align__(128) __half g_ac[(size_t)ACOLS*HID];      // A_cat 384x2048
__device__ __align__(128) __half g_h2[(size_t)T_TOK*ACOLS];
__device__ int g_is64;

#define DINL __device__ __forceinline__

DINL uint32_t smem_u32(const void* p){ uint32_t a;
  asm("{ .reg .u64 t; cvta.to.shared.u64 t, %1; cvt.u32.u64 %0, t; }":"=r"(a):"l"(p)); return a; }

DINL uint32_t swz(uint32_t off){ return off ^ ((off>>3)&0x70); }

DINL void ldmx4(uint32_t* r, uint32_t addr){
  asm volatile("ldmatrix.sync.aligned.m8n8.x4.shared.b16 {%0,%1,%2,%3}, [%4];"
    : "=r"(r[0]),"=r"(r[1]),"=r"(r[2]),"=r"(r[3]) : "r"(addr));
}

DINL void mma16816(float* c, const uint32_t* a, const uint32_t* b){
  asm volatile("mma.sync.aligned.m16n8k16.row.col.f32.f16.f16.f32 "
    "{%0,%1,%2,%3},{%4,%5,%6,%7},{%8,%9},{%0,%1,%2,%3};"
    : "+f"(c[0]),"+f"(c[1]),"+f"(c[2]),"+f"(c[3])
    : "r"(a[0]),"r"(a[1]),"r"(a[2]),"r"(a[3]),"r"(b[0]),"r"(b[1]));
}

#define CPA_COMMIT() asm volatile("cp.async.commit_group;\n":::"memory")
#define CPA_WAIT1()  asm volatile("cp.async.wait_group 1;\n":::"memory")

// load 128 x 64 fp16 (128B rows) into SW128-swizzled SMEM via cp.async; 256 threads
DINL void load_tile(uint32_t dst, const __half* g, long rowBase, int ld, int k0, int tid){
  const char* s0 = (const char*)(g + rowBase*(long)ld + k0);
  const long rb = (long)ld*2;
  #pragma unroll
  for(int c=tid; c<128*8; c+=256){
    int row=c>>3, ck=c&7;
    uint32_t off=(uint32_t)(row*128+ck*16);
    const void* src = s0 + (long)row*rb + ck*16;
    asm volatile("cp.async.cg.shared.global [%0], [%1], 16;\n"::"r"(dst+swz(off)),"l"(src):"memory");
  }
}

static constexpr uint32_t TILE_B = 128*128;        // 16 KB per tile
static constexpr uint32_t STAGE  = 2*TILE_B;       // A + B = 32 KB
static constexpr int      NSTG   = 3;
static constexpr uint32_t SMEM_TOTAL = NSTG*STAGE; // 96 KB -> 2 CTAs/SM

// MODE 1: fused GEMM1 — first nkx K-iters from A, rest from A2 (H2 slice).
//         Epilogue: plain y store to out.
// MODE 3: GEMM0 — epilogue: slot-mask + scale -> H2 fp16 write.
template<int MODE>
__global__ void __launch_bounds__(256,2)
gemm_k(const __half* __restrict__ A, int lda,
       const __half* __restrict__ A2, int lda2,
       const __half* __restrict__ B, int ldb,
       float* __restrict__ out, int NK, int nkx,
       const unsigned int* __restrict__ tts, const float* __restrict__ scal,
       __half* __restrict__ h2){
  extern __shared__ __align__(1024) char smem[];
  const uint32_t sb = smem_u32(smem);
  const int tid=threadIdx.x, lane=tid&31, wid=tid>>5;
  const int wm=wid>>2, wn=wid&3;                 // 2 x 4 warp grid -> m64 x n32 warp tile
  const long mB=(long)blockIdx.y*BM, nB=(long)blockIdx.x*BN;
  const int gofs = (MODE==1) ? ((nB>=2560)?256:((nB>=2048)?128:0)) : 0;

  auto st=[&](int s){ return sb + (uint32_t)s*STAGE; };
  auto load_st=[&](int s,int ki){
    uint32_t a=st(s);
    if(MODE==1 && ki>=nkx) load_tile(a, A2, mB, lda2, gofs + (ki-nkx)*BK, tid);
    else                   load_tile(a, A,  mB, lda,  ki*BK, tid);
    load_tile(a+TILE_B, B, nB, ldb, ki*BK, tid);
  };

  float c[4][4][4];
  #pragma unroll
  for(int i=0;i<4;i++)
    #pragma unroll
    for(int j=0;j<4;j++)
      #pragma unroll
      for(int e=0;e<4;e++) c[i][j][e]=0.f;

  const int rowA = (lane&15);
  const int cA   = (lane>>4);
  const int rowB = (lane&7) + ((lane>>4)&1)*8;
  const int cB   = (lane>>3)&1;

  // prologue: 2 stages in flight
  load_st(0,0); CPA_COMMIT();
  load_st(1,1); CPA_COMMIT();

  #pragma unroll 1
  for(int ki=0; ki<NK; ki++){
    CPA_WAIT1();
    __syncthreads();
    if(ki+2<NK) load_st((ki+2)%NSTG, ki+2);
    CPA_COMMIT();

    const uint32_t a0 = st(ki%NSTG);
    #pragma unroll 1
    for(int kk=0; kk<4; kk++){
      uint32_t af[4][4], bf[4][2];
      #pragma unroll
      for(int mt=0; mt<4; mt++){
        uint32_t off=(uint32_t)((wm*64+mt*16+rowA)*128 + (kk*2+cA)*16);
        ldmx4(af[mt], a0 + swz(off));
      }
      #pragma unroll
      for(int p=0; p<2; p++){
        uint32_t off=(uint32_t)((wn*32+p*16+rowB)*128 + (kk*2+cB)*16);
        uint32_t t[4];
        ldmx4(t, a0 + TILE_B + swz(off));
        bf[2*p][0]=t[0]; bf[2*p][1]=t[1]; bf[2*p+1][0]=t[2]; bf[2*p+1][1]=t[3];
      }
      #pragma unroll
      for(int nt=0; nt<4; nt++)
        #pragma unroll
        for(int mt=0; mt<4; mt++) mma16816(c[mt][nt], af[mt], bf[nt]);
    }
  }

  // ------------- epilogue -------------
  const int r0 = wm*64 + (lane>>2);
  const int cc0 = wn*32 + (lane&3)*2;
  if(MODE==3){
    #pragma unroll
    for(int mt=0; mt<4; mt++)
      #pragma unroll
      for(int h=0; h<2; h++){
        long row = mB + r0 + mt*16 + h*8;
        int slot = g_is64 ? (int)tts[2*row] : (int)tts[row];
        float sc = scal[slot];
        #pragma unroll
        for(int nt=0; nt<4; nt++){
          int a = (int)nB + cc0 + nt*8;
          int l = (a>>4)&7;
          float v0 = (l==slot)? sc*c[mt][nt][h*2]   : 0.f;
          float v1 = (l==slot)? sc*c[mt][nt][h*2+1] : 0.f;
          *(__half2*)(h2 + row*ACOLS + a) = __floats2half2_rn(v0, v1);
        }
      }
  } else {
    #pragma unroll
    for(int mt=0; mt<4; mt++)
      #pragma unroll
      for(int h=0; h<2; h++){
        long row = mB + r0 + mt*16 + h*8;
        float2* base=(float2*)(out + row*OUTC + nB + cc0);
        #pragma unroll
        for(int nt=0; nt<4; nt++)
          base[nt*4] = make_float2(c[mt][nt][h*2], c[mt][nt][h*2+1]);
      }
  }
}

// ---------------- prep kernels ----------------
__global__ void k_cvt_x(const float* __restrict__ x, __half* __restrict__ xf, int n4){
  int i=blockIdx.x*blockDim.x+threadIdx.x; if(i>=n4) return;
  float4 v=((const float4*)x)[i];
  ((__half2*)xf)[2*i]  =__floats2half2_rn(v.x,v.y);
  ((__half2*)xf)[2*i+1]=__floats2half2_rn(v.z,v.w);
}

// one block per output row; W part vectorized float4, 128-col Ball tail
__global__ void k_build_w2(const float* __restrict__ w, const float* __restrict__ bq,
                           const float* __restrict__ bk, const float* __restrict__ bv,
                           __half* __restrict__ w2){
  const int row = blockIdx.x;
  const int tid = threadIdx.x;
  const float4* src = (const float4*)(w + (long)row*HID);
  __half2* dst = (__half2*)(w2 + (long)row*KEXT);
  #pragma unroll
  for(int k4 = tid; k4 < HID/4; k4 += 256){
    float4 v = src[k4];
    dst[2*k4]   = __floats2half2_rn(v.x, v.y);
    dst[2*k4+1] = __floats2half2_rn(v.z, v.w);
  }
  if(tid < 128){
    int l = tid>>4, r = tid&15;
    float v;
    if(row<2048)      v=bq[((long)l*2048+row)*16+r];
    else if(row<2560) v=bk[((long)l*512+(row-2048))*16+r];
    else              v=bv[((long)l*512+(row-2560))*16+r];
    w2[(long)row*KEXT + HID + tid] = __float2half_rn(v);
  }
}

// A_cat rows: a = g*128 + l*16 + r -> lora_A[l, g, r, :]
__global__ void k_build_acat(const float* __restrict__ la, __half* __restrict__ ac){
  int i=blockIdx.x*blockDim.x+threadIdx.x; if(i>=ACOLS*HID) return;
  int row=i>>11, k=i&2047;
  int g=row>>7, l=(row>>4)&7, r=row&15;
  ac[i]=__float2half_rn(la[(((long)l*3+g)*16+r)*HID+k]);
}

// token_to_slot dtype sniff: slots<8, so int64 => all odd 32-bit words are 0
__global__ void k_detect(const unsigned int* __restrict__ w){
  __shared__ int found;
  if(threadIdx.x==0) found=0;
  __syncthreads();
  int loc=0;
  for(int i=1+2*(int)threadIdx.x; i<T_TOK; i+=1024) loc|=(w[i]!=0u);
  if(loc) atomicOr(&found,1);
  __syncthreads();
  if(threadIdx.x==0) g_is64 = found?0:1;
}

extern "C" void kernel_launch(void* const* d_in, const int* in_sizes, int n_in,
                              void* d_out, int out_size){
  (void)in_sizes; (void)n_in; (void)out_size;
  const float* x =(const float*)d_in[0];
  const float* w =(const float*)d_in[1];
  const float* la=(const float*)d_in[2];
  const float* bq=(const float*)d_in[3];
  const float* bk=(const float*)d_in[4];
  const float* bv=(const float*)d_in[5];
  const float* sc=(const float*)d_in[6];
  const unsigned int* tt=(const unsigned int*)d_in[7];
  float* out=(float*)d_out;

  void *xf,*w2,*ac,*h2;
  cudaGetSymbolAddress(&xf,g_xf); cudaGetSymbolAddress(&w2,g_w2);
  cudaGetSymbolAddress(&ac,g_ac); cudaGetSymbolAddress(&h2,g_h2);

  cudaFuncSetAttribute(gemm_k<1>, cudaFuncAttributeMaxDynamicSharedMemorySize, SMEM_TOTAL);
  cudaFuncSetAttribute(gemm_k<3>, cudaFuncAttributeMaxDynamicSharedMemorySize, SMEM_TOTAL);

  k_detect<<<1,512>>>(tt);
  k_cvt_x<<<(T_TOK*HID/4+255)/256,256>>>(x,(__half*)xf,T_TOK*HID/4);
  k_build_acat<<<(ACOLS*HID+255)/256,256>>>(la,(__half*)ac);
  k_build_w2<<<OUTC,256>>>(w,bq,bk,bv,(__half*)w2);

  // GEMM0: H2[8192 x 384] = mask/scale( X @ A_cat^T )
  gemm_k<3><<<dim3(ACOLS/BN, T_TOK/BM), 256, SMEM_TOTAL>>>(
      (const __half*)xf, HID, nullptr, 0, (const __half*)ac, HID,
      nullptr, HID/BK, HID/BK, tt, sc, (__half*)h2);

  // GEMM1 fused: out[8192 x 3072] = [X | H2_g] @ [W | Ball_g]^T  (K = 2176)
  gemm_k<1><<<dim3(OUTC/BN, T_TOK/BM), 256, SMEM_TOTAL>>>(
      (const __half*)xf, HID, (const __half*)h2, ACOLS, (const __half*)w2, KEXT,
      out, KEXT/BK, HID/BK, tt, sc, nullptr);
}